// round 16
// baseline (speedup 1.0000x reference)
#include <cuda_runtime.h>
#include <cuda_fp16.h>
#include <cstdint>
#include <cstddef>

// ---------------------------------------------------------------------------
// Problem constants
// ---------------------------------------------------------------------------
#define BATCH   4096
#define TT      2
#define NTOK    49
#define CDIM    192
#define NHEAD   6
#define HDIM    32

#define M_Q   (BATCH * NTOK)          // 200704
#define M_KV  (BATCH * TT * NTOK)     // 401408

// Scratch (device globals, fp16 intermediates), 16B-aligned for uint4 access
__device__ __align__(16) __half g_q [(size_t)M_Q  * CDIM];          //  77 MB
__device__ __align__(16) __half g_kv[(size_t)M_KV * 2 * CDIM];      // 308 MB
__device__ __align__(16) __half g_ao[(size_t)M_KV * CDIM];          // 154 MB
// fp16 weights (converted once per launch)
__device__ __align__(16) __half g_wq16 [CDIM * CDIM];
__device__ __align__(16) __half g_wkv16[2 * CDIM * CDIM];
__device__ __align__(16) __half g_wp16 [CDIM * CDIM];

// ---------------------------------------------------------------------------
// Helpers
// ---------------------------------------------------------------------------
__device__ __forceinline__ void mma_f16(float* d, const uint32_t* a,
                                        uint32_t b0, uint32_t b1) {
    asm volatile(
        "mma.sync.aligned.m16n8k16.row.col.f32.f16.f16.f32 "
        "{%0,%1,%2,%3}, {%4,%5,%6,%7}, {%8,%9}, {%0,%1,%2,%3};"
        : "+f"(d[0]), "+f"(d[1]), "+f"(d[2]), "+f"(d[3])
        : "r"(a[0]), "r"(a[1]), "r"(a[2]), "r"(a[3]), "r"(b0), "r"(b1));
}
__device__ __forceinline__ uint32_t h2u(float x, float y) {  // rn-packed half2
    __half2 h = __floats2half2_rn(x, y);
    return *reinterpret_cast<uint32_t*>(&h);
}
__device__ __forceinline__ uint32_t smem_u32(const void* p) {
    uint32_t a;
    asm("{ .reg .u64 t; cvta.to.shared.u64 t, %1; cvt.u32.u64 %0, t; }" : "=r"(a) : "l"(p));
    return a;
}
__device__ __forceinline__ void cp16(uint32_t dst, const void* src) {
    asm volatile("cp.async.cg.shared.global [%0], [%1], 16;" :: "r"(dst), "l"(src));
}
__device__ __forceinline__ void ldsm4(uint32_t* r, uint32_t addr) {
    asm volatile("ldmatrix.sync.aligned.m8n8.x4.shared.b16 {%0,%1,%2,%3}, [%4];"
                 : "=r"(r[0]), "=r"(r[1]), "=r"(r[2]), "=r"(r[3]) : "r"(addr));
}
__device__ __forceinline__ void ldsm2(uint32_t* r, uint32_t addr) {
    asm volatile("ldmatrix.sync.aligned.m8n8.x2.shared.b16 {%0,%1}, [%2];"
                 : "=r"(r[0]), "=r"(r[1]) : "r"(addr));
}
__device__ __forceinline__ void ldsm4t(uint32_t* r, uint32_t addr) {
    asm volatile("ldmatrix.sync.aligned.m8n8.x4.trans.shared.b16 {%0,%1,%2,%3}, [%4];"
                 : "=r"(r[0]), "=r"(r[1]), "=r"(r[2]), "=r"(r[3]) : "r"(addr));
}

// ---------------------------------------------------------------------------
// Weight fp32 -> fp16 conversion (once per launch; ~3us)
// ---------------------------------------------------------------------------
__global__ void cvt_w(const float* __restrict__ wq, const float* __restrict__ wkv,
                      const float* __restrict__ wp) {
    const int i = blockIdx.x * blockDim.x + threadIdx.x;
    if (i < CDIM * CDIM)     g_wq16[i] = __float2half_rn(wq[i]);
    if (i < 2 * CDIM * CDIM) g_wkv16[i] = __float2half_rn(wkv[i]);
    if (i < CDIM * CDIM)     g_wp16[i] = __float2half_rn(wp[i]);
}

// ---------------------------------------------------------------------------
// Tensor-core GEMM (unchanged from R13): mma.sync fp16 + ldmatrix + cp.async.
// ---------------------------------------------------------------------------
#define RSW   36
#define AWSZ  (128 * RSW)
#define WWSZ  (192 * RSW)
#define GEMM_SMEM ((2 * AWSZ + 2 * WWSZ) * 4)   // 92160 bytes

template<int NCTOT, bool AHALF, bool OHALF>
__global__ __launch_bounds__(512)
void gemm_mma(const void* __restrict__ Ain, const __half* __restrict__ Wh,
              const float* __restrict__ bias, void* __restrict__ outv,
              float outScale)
{
    extern __shared__ uint32_t smw[];
    const uint32_t smb = smem_u32(smw);
    const int tid  = threadIdx.x;
    const int wid  = tid >> 5;
    const int lane = tid & 31;
    const int wm   = wid & 3;
    const int wn   = wid >> 2;
    const int gid  = lane >> 2;
    const int tc   = lane & 3;

    const size_t mbase = (size_t)blockIdx.x * 128;
    const int    nbase = blockIdx.y * 192;
    const float*  Af = (const float*)Ain + mbase * CDIM;
    const __half* Ah = (const __half*)Ain + mbase * CDIM;
    const __half* Wblk = Wh + (size_t)nbase * CDIM;

    const uint32_t stA[2] = { smb, smb + AWSZ * 4 };
    const uint32_t stW[2] = { smb + 2 * AWSZ * 4, smb + (2 * AWSZ + WWSZ) * 4 };

    float acc[2][6][4];
#pragma unroll
    for (int mi = 0; mi < 2; mi++)
#pragma unroll
        for (int ni = 0; ni < 6; ni++)
#pragma unroll
            for (int j = 0; j < 4; j++) acc[mi][ni][j] = 0.f;

    const int prow = tid >> 2;
    const int psub = tid & 3;
    float4 apf[4];

    auto issueW = [&](int c, int st) {
        const int ko = c * 64;
#pragma unroll
        for (int k = 0; k < 3; k++) {
            const int i = tid + k * 512;
            const int r = i >> 3, g = i & 7;
            cp16(stW[st] + (uint32_t)(r * RSW + g * 4) * 4, Wblk + (size_t)r * CDIM + ko + g * 8);
        }
    };
    auto issueA_h = [&](int c, int st) {
        const int ko = c * 64;
        cp16(stA[st] + (uint32_t)(prow * RSW + psub * 4) * 4,
             Ah + (size_t)prow * CDIM + ko + psub * 8);
        cp16(stA[st] + (uint32_t)(prow * RSW + (psub + 4) * 4) * 4,
             Ah + (size_t)prow * CDIM + ko + (psub + 4) * 8);
    };
    auto ldgA_f = [&](int c) {
        const int ko = c * 64 + psub * 16;
#pragma unroll
        for (int j = 0; j < 4; j++)
            apf[j] = *(const float4*)(Af + (size_t)prow * CDIM + ko + j * 4);
    };
    auto stsA_f = [&](int st) {
        uint32_t* sA = smw + (stA[st] - smb) / 4;
#pragma unroll
        for (int j = 0; j < 4; j++) {
            uint2 p = { h2u(apf[j].x, apf[j].y), h2u(apf[j].z, apf[j].w) };
            *(uint2*)&sA[prow * RSW + psub * 8 + j * 2] = p;
        }
    };

    if (AHALF) { issueA_h(0, 0); } else { ldgA_f(0); }
    issueW(0, 0);
    asm volatile("cp.async.commit_group;" ::: "memory");
    if (!AHALF) stsA_f(0);
    asm volatile("cp.async.wait_group 0;" ::: "memory");
    __syncthreads();

    const uint32_t a_lane = ((uint32_t)(wm * 32 + ((lane >> 3) & 1) * 8 + (lane & 7)) * RSW
                            + (lane >> 4) * 4) * 4;
    const uint32_t b_lane = ((uint32_t)(wn * 48 + (lane >> 4) * 8 + (lane & 7)) * RSW
                            + ((lane >> 3) & 1) * 4) * 4;

#pragma unroll 1
    for (int c = 0; c < 3; c++) {
        const int st = c & 1;
        if (c < 2) {
            if (AHALF) issueA_h(c + 1, st ^ 1); else ldgA_f(c + 1);
            issueW(c + 1, st ^ 1);
            asm volatile("cp.async.commit_group;" ::: "memory");
        }
#pragma unroll
        for (int t = 0; t < 4; t++) {
            uint32_t a[2][4], bb[3][4];
#pragma unroll
            for (int mi = 0; mi < 2; mi++)
                ldsm4(a[mi], stA[st] + a_lane + (uint32_t)(mi * 16 * RSW + t * 8) * 4);
#pragma unroll
            for (int p = 0; p < 3; p++)
                ldsm4(bb[p], stW[st] + b_lane + (uint32_t)(p * 16 * RSW + t * 8) * 4);
#pragma unroll
            for (int p = 0; p < 3; p++) {
                mma_f16(acc[0][2 * p],     a[0], bb[p][0], bb[p][1]);
                mma_f16(acc[1][2 * p],     a[1], bb[p][0], bb[p][1]);
                mma_f16(acc[0][2 * p + 1], a[0], bb[p][2], bb[p][3]);
                mma_f16(acc[1][2 * p + 1], a[1], bb[p][2], bb[p][3]);
            }
        }
        if (c < 2) {
            if (!AHALF) stsA_f(st ^ 1);
            asm volatile("cp.async.wait_group 0;" ::: "memory");
            __syncthreads();
        }
    }

#pragma unroll
    for (int mi = 0; mi < 2; mi++) {
#pragma unroll
        for (int ni = 0; ni < 6; ni++) {
            const size_t row = mbase + wm * 32 + mi * 16 + gid;
            const int    col = nbase + wn * 48 + ni * 8 + tc * 2;
            const float2 bb2 = *(const float2*)&bias[col];
            float v0 = (acc[mi][ni][0] + bb2.x) * outScale;
            float v1 = (acc[mi][ni][1] + bb2.y) * outScale;
            float v2 = (acc[mi][ni][2] + bb2.x) * outScale;
            float v3 = (acc[mi][ni][3] + bb2.y) * outScale;
            if (OHALF) {
                __half* o = (__half*)outv;
                *(uint32_t*)&o[(row    ) * NCTOT + col] = h2u(v0, v1);
                *(uint32_t*)&o[(row + 8) * NCTOT + col] = h2u(v2, v3);
            } else {
                float* o = (float*)outv;
                float2 r0 = {v0, v1}, r1 = {v2, v3};
                *(float2*)&o[(row    ) * NCTOT + col] = r0;
                *(float2*)&o[(row + 8) * NCTOT + col] = r1;
            }
        }
    }
}

// ---------------------------------------------------------------------------
// fp16 attention, one CTA per (b,t): 24 warps, warp = (head, m-tile).
// Per-warp state is 1 m16 tile -> ~90 regs, 24 warps/SM (vs 12 in R15).
// Q/K/V raw token rows (stride 20 words), pad rows zeroed; ldmatrix loads;
// register softmax with separable bias.  smem = 6 heads x 15.4 KB = 92.4 KB.
// ---------------------------------------------------------------------------
#define TSTR    20
#define OFF_K   (64 * TSTR)                       // 1280
#define OFF_V   (OFF_K + 56 * TSTR)               // 2400
#define OFF_RPB (OFF_V + 64 * TSTR)               // 3680
#define HEADW   (OFF_RPB + 172)                   // 3852 words (16B-aligned)
#define ATTN_SMEM (NHEAD * HEADW * 4)             // 92448 bytes

__global__ __launch_bounds__(768)
void attn_mma(const __half* __restrict__ Q, const __half* __restrict__ KV,
              const float* __restrict__ rpb, __half* __restrict__ O)
{
    extern __shared__ uint32_t smw[];
    const int tid  = threadIdx.x;
    const int lane = tid & 31;
    const int h    = tid >> 7;          // head 0..5 (128 threads each)
    const int mi   = (tid >> 5) & 3;    // m-tile 0..3
    const int wtid = tid & 127;         // thread within head group
    const int gid  = lane >> 2;
    const int tc   = lane & 3;
    const int bt   = blockIdx.x;
    const int b    = bt >> 1;

    uint32_t* sQ  = smw + h * HEADW;
    uint32_t* sK  = sQ + OFF_K;
    uint32_t* sV  = sQ + OFF_V;
    float*    srpb = (float*)(sQ + OFF_RPB);
    const uint32_t sQb = smem_u32(sQ);
    const uint32_t sKb = smem_u32(sK);
    const uint32_t sVb = smem_u32(sV);

    // ---- per-head loads by this head's 128 threads ----
    for (int i = wtid; i < 169; i += 128) srpb[i] = rpb[i * NHEAD + h];

    const uint4 z4 = {0u, 0u, 0u, 0u};
    if (wtid < 75) *(uint4*)&sQ[980 + wtid * 4] = z4;
    if (wtid < 35) *(uint4*)&sK[980 + wtid * 4] = z4;
    if (wtid < 75) *(uint4*)&sV[980 + wtid * 4] = z4;

    for (int i = wtid; i < NTOK * 4; i += 128) {
        const int n = i >> 2, g = i & 3;
        *(uint4*)&sQ[n * TSTR + g * 4] =
            *(const uint4*)&Q[((size_t)(b * NTOK + n)) * CDIM + h * HDIM + g * 8];
        const size_t kb = (size_t)(bt * NTOK + n) * (2 * CDIM) + h * HDIM + g * 8;
        *(uint4*)&sK[n * TSTR + g * 4] = *(const uint4*)&KV[kb];
        *(uint4*)&sV[n * TSTR + g * 4] = *(const uint4*)&KV[kb + CDIM];
    }
    __syncthreads();

    const int l15 = lane & 15, l7 = lane & 7;
    const int g16 = lane >> 4, g8 = (lane >> 3) & 1;

    // ---- S = Q K^T for this warp's m16 tile (scale pre-folded into Q) ----
    float sf[7][4];
#pragma unroll
    for (int ni = 0; ni < 7; ni++)
#pragma unroll
        for (int j = 0; j < 4; j++) sf[ni][j] = 0.f;

#pragma unroll
    for (int t = 0; t < 2; t++) {
        uint32_t a[4];
        ldsm4(a, sQb + (uint32_t)((16 * mi + l15) * TSTR + t * 8 + g16 * 4) * 4);
        uint32_t bb[4][4];
#pragma unroll
        for (int p = 0; p < 3; p++)
            ldsm4(bb[p], sKb + (uint32_t)((8 * (2 * p + g16) + l7) * TSTR + t * 8 + g8 * 4) * 4);
        ldsm2(bb[3], sKb + (uint32_t)((48 + l7) * TSTR + t * 8 + g8 * 4) * 4);
#pragma unroll
        for (int p = 0; p < 3; p++) {
            mma_f16(sf[2 * p],     a, bb[p][0], bb[p][1]);
            mma_f16(sf[2 * p + 1], a, bb[p][2], bb[p][3]);
        }
        mma_f16(sf[6], a, bb[3][0], bb[3][1]);
    }

    // ---- register softmax + pack to PV A-fragments ----
    uint32_t pf[4][4];
#pragma unroll
    for (int jp = 0; jp < 2; jp++) {
        const int n = 16 * mi + 8 * jp + gid;
        const bool vrow = (n < NTOK);
        const int fn = 13 * (n / 7) + (n % 7);
        float vv[7][2];
        float mx = -1e30f;
#pragma unroll
        for (int ni = 0; ni < 7; ni++) {
#pragma unroll
            for (int jc = 0; jc < 2; jc++) {
                const int m = 8 * ni + 2 * tc + jc;
                float v = sf[ni][jp * 2 + jc];
                if (vrow && m < NTOK) {
                    const int fm = 13 * (m / 7) + (m % 7);
                    v += srpb[fn - fm + 84];
                } else {
                    v = -1e30f;
                }
                vv[ni][jc] = v;
                mx = fmaxf(mx, v);
            }
        }
        mx = fmaxf(mx, __shfl_xor_sync(0xffffffffu, mx, 1));
        mx = fmaxf(mx, __shfl_xor_sync(0xffffffffu, mx, 2));
        float sum = 0.f;
#pragma unroll
        for (int ni = 0; ni < 7; ni++)
#pragma unroll
            for (int jc = 0; jc < 2; jc++) {
                float e = __expf(vv[ni][jc] - mx);
                vv[ni][jc] = e;
                sum += e;
            }
        sum += __shfl_xor_sync(0xffffffffu, sum, 1);
        sum += __shfl_xor_sync(0xffffffffu, sum, 2);
        const float inv = vrow ? (1.f / sum) : 0.f;
#pragma unroll
        for (int t = 0; t < 4; t++) {
            pf[t][jp] = h2u(vv[2 * t][0] * inv, vv[2 * t][1] * inv);
            pf[t][2 + jp] = (2 * t + 1 < 7)
                ? h2u(vv[2 * t + 1][0] * inv, vv[2 * t + 1][1] * inv) : 0u;
        }
    }

    // ---- O = P V: B = V^T via ldsm4.trans on raw V rows ----
    float of[4][4];
#pragma unroll
    for (int nd = 0; nd < 4; nd++)
#pragma unroll
        for (int j = 0; j < 4; j++) of[nd][j] = 0.f;

#pragma unroll
    for (int t = 0; t < 4; t++) {
        uint32_t bb[2][4];
#pragma unroll
        for (int q = 0; q < 2; q++)
            ldsm4t(bb[q], sVb + (uint32_t)((t * 16 + g8 * 8 + l7) * TSTR + (2 * q + g16) * 4) * 4);
#pragma unroll
        for (int q = 0; q < 2; q++) {
            mma_f16(of[2 * q],     pf[t], bb[q][0], bb[q][1]);
            mma_f16(of[2 * q + 1], pf[t], bb[q][2], bb[q][3]);
        }
    }

    // Store O head slice (half2 words)
    const int r0 = 16 * mi + gid;
#pragma unroll
    for (int nd = 0; nd < 4; nd++) {
        const int col = h * HDIM + nd * 8 + 2 * tc;
        if (r0 < NTOK)
            *(uint32_t*)&O[((size_t)(bt * NTOK + r0)) * CDIM + col] =
                h2u(of[nd][0], of[nd][1]);
        if (r0 + 8 < NTOK)
            *(uint32_t*)&O[((size_t)(bt * NTOK + r0 + 8)) * CDIM + col] =
                h2u(of[nd][2], of[nd][3]);
    }
}

// ---------------------------------------------------------------------------
// kernel_launch
// ---------------------------------------------------------------------------
extern "C" void kernel_launch(void* const* d_in, const int* in_sizes, int n_in,
                              void* d_out, int out_size)
{
    const float* x      = (const float*)d_in[0];
    const float* memory = (const float*)d_in[1];
    const float* w_q    = (const float*)d_in[2];
    const float* b_q    = (const float*)d_in[3];
    const float* w_kv   = (const float*)d_in[4];
    const float* b_kv   = (const float*)d_in[5];
    const float* w_proj = (const float*)d_in[6];
    const float* b_proj = (const float*)d_in[7];
    const float* rpb    = (const float*)d_in[8];

    __half *gq, *gkv, *gao, *wq16, *wkv16, *wp16;
    cudaGetSymbolAddress((void**)&gq,    g_q);
    cudaGetSymbolAddress((void**)&gkv,   g_kv);
    cudaGetSymbolAddress((void**)&gao,   g_ao);
    cudaGetSymbolAddress((void**)&wq16,  g_wq16);
    cudaGetSymbolAddress((void**)&wkv16, g_wkv16);
    cudaGetSymbolAddress((void**)&wp16,  g_wp16);

    cudaFuncSetAttribute((const void*)gemm_mma<192, false, true>,
                         cudaFuncAttributeMaxDynamicSharedMemorySize, GEMM_SMEM);
    cudaFuncSetAttribute((const void*)gemm_mma<384, false, true>,
                         cudaFuncAttributeMaxDynamicSharedMemorySize, GEMM_SMEM);
    cudaFuncSetAttribute((const void*)gemm_mma<192, true, false>,
                         cudaFuncAttributeMaxDynamicSharedMemorySize, GEMM_SMEM);
    cudaFuncSetAttribute((const void*)attn_mma,
                         cudaFuncAttributeMaxDynamicSharedMemorySize, ATTN_SMEM);

    const float scale = 0.17677669529663687f;   // 32^-0.5, folded into Q

    cvt_w<<<(2 * CDIM * CDIM + 255) / 256, 256>>>(w_q, w_kv, w_proj);

    gemm_mma<192, false, true><<<dim3(M_Q / 128, 1), 512, GEMM_SMEM>>>(
        x, wq16, b_q, gq, scale);
    gemm_mma<384, false, true><<<dim3(M_KV / 128, 2), 512, GEMM_SMEM>>>(
        memory, wkv16, b_kv, gkv, 1.0f);
    attn_mma<<<BATCH * TT, 768, ATTN_SMEM>>>(gq, gkv, rpb, gao);
    gemm_mma<192, true, false><<<dim3(M_KV / 128, 1), 512, GEMM_SMEM>>>(
        gao, wp16, b_proj, d_out, 1.0f);
}

// round 17
// speedup vs baseline: 1.0723x; 1.0723x over previous
#include <cuda_runtime.h>
#include <cuda_fp16.h>
#include <cstdint>
#include <cstddef>

// ---------------------------------------------------------------------------
// Problem constants
// ---------------------------------------------------------------------------
#define BATCH   4096
#define TT      2
#define NTOK    49
#define CDIM    192
#define NHEAD   6
#define HDIM    32

#define M_Q   (BATCH * NTOK)          // 200704
#define M_KV  (BATCH * TT * NTOK)     // 401408

// Scratch (device globals, fp16 intermediates), 16B-aligned for uint4 access
__device__ __align__(16) __half g_q [(size_t)M_Q  * CDIM];          //  77 MB
__device__ __align__(16) __half g_kv[(size_t)M_KV * 2 * CDIM];      // 308 MB
__device__ __align__(16) __half g_ao[(size_t)M_KV * CDIM];          // 154 MB
// fp16 weights (converted once per launch)
__device__ __align__(16) __half g_wq16 [CDIM * CDIM];
__device__ __align__(16) __half g_wkv16[2 * CDIM * CDIM];
__device__ __align__(16) __half g_wp16 [CDIM * CDIM];

// ---------------------------------------------------------------------------
// Helpers
// ---------------------------------------------------------------------------
__device__ __forceinline__ void mma_f16(float* d, const uint32_t* a,
                                        uint32_t b0, uint32_t b1) {
    asm volatile(
        "mma.sync.aligned.m16n8k16.row.col.f32.f16.f16.f32 "
        "{%0,%1,%2,%3}, {%4,%5,%6,%7}, {%8,%9}, {%0,%1,%2,%3};"
        : "+f"(d[0]), "+f"(d[1]), "+f"(d[2]), "+f"(d[3])
        : "r"(a[0]), "r"(a[1]), "r"(a[2]), "r"(a[3]), "r"(b0), "r"(b1));
}
__device__ __forceinline__ uint32_t h2u(float x, float y) {  // rn-packed half2
    __half2 h = __floats2half2_rn(x, y);
    return *reinterpret_cast<uint32_t*>(&h);
}
__device__ __forceinline__ uint32_t smem_u32(const void* p) {
    uint32_t a;
    asm("{ .reg .u64 t; cvta.to.shared.u64 t, %1; cvt.u32.u64 %0, t; }" : "=r"(a) : "l"(p));
    return a;
}
__device__ __forceinline__ void cp16(uint32_t dst, const void* src) {
    asm volatile("cp.async.cg.shared.global [%0], [%1], 16;" :: "r"(dst), "l"(src));
}
__device__ __forceinline__ void ldsm4(uint32_t* r, uint32_t addr) {
    asm volatile("ldmatrix.sync.aligned.m8n8.x4.shared.b16 {%0,%1,%2,%3}, [%4];"
                 : "=r"(r[0]), "=r"(r[1]), "=r"(r[2]), "=r"(r[3]) : "r"(addr));
}
__device__ __forceinline__ void ldsm2(uint32_t* r, uint32_t addr) {
    asm volatile("ldmatrix.sync.aligned.m8n8.x2.shared.b16 {%0,%1}, [%2];"
                 : "=r"(r[0]), "=r"(r[1]) : "r"(addr));
}
__device__ __forceinline__ void ldsm4t(uint32_t* r, uint32_t addr) {
    asm volatile("ldmatrix.sync.aligned.m8n8.x4.trans.shared.b16 {%0,%1,%2,%3}, [%4];"
                 : "=r"(r[0]), "=r"(r[1]), "=r"(r[2]), "=r"(r[3]) : "r"(addr));
}

// ---------------------------------------------------------------------------
// Weight fp32 -> fp16 conversion (once per launch; ~3us)
// ---------------------------------------------------------------------------
__global__ void cvt_w(const float* __restrict__ wq, const float* __restrict__ wkv,
                      const float* __restrict__ wp) {
    const int i = blockIdx.x * blockDim.x + threadIdx.x;
    if (i < CDIM * CDIM)     g_wq16[i] = __float2half_rn(wq[i]);
    if (i < 2 * CDIM * CDIM) g_wkv16[i] = __float2half_rn(wkv[i]);
    if (i < CDIM * CDIM)     g_wp16[i] = __float2half_rn(wp[i]);
}

// ---------------------------------------------------------------------------
// Tensor-core GEMM (R13 core): mma.sync fp16 + ldmatrix + cp.async.
// GRID SWAP (R17): blockIdx.x = column block (fastest), blockIdx.y = M block,
// so for NC=384 the two column blocks of one M block run back-to-back and the
// second one's A-read hits L2 instead of DRAM (saves 308 MB on the KV GEMM).
// ---------------------------------------------------------------------------
#define RSW   36
#define AWSZ  (128 * RSW)
#define WWSZ  (192 * RSW)
#define GEMM_SMEM ((2 * AWSZ + 2 * WWSZ) * 4)   // 92160 bytes

template<int NCTOT, bool AHALF, bool OHALF>
__global__ __launch_bounds__(512)
void gemm_mma(const void* __restrict__ Ain, const __half* __restrict__ Wh,
              const float* __restrict__ bias, void* __restrict__ outv,
              float outScale)
{
    extern __shared__ uint32_t smw[];
    const uint32_t smb = smem_u32(smw);
    const int tid  = threadIdx.x;
    const int wid  = tid >> 5;
    const int lane = tid & 31;
    const int wm   = wid & 3;
    const int wn   = wid >> 2;
    const int gid  = lane >> 2;
    const int tc   = lane & 3;

    const size_t mbase = (size_t)blockIdx.y * 128;     // M block (outer)
    const int    nbase = blockIdx.x * 192;             // column block (inner)
    const float*  Af = (const float*)Ain + mbase * CDIM;
    const __half* Ah = (const __half*)Ain + mbase * CDIM;
    const __half* Wblk = Wh + (size_t)nbase * CDIM;

    const uint32_t stA[2] = { smb, smb + AWSZ * 4 };
    const uint32_t stW[2] = { smb + 2 * AWSZ * 4, smb + (2 * AWSZ + WWSZ) * 4 };

    float acc[2][6][4];
#pragma unroll
    for (int mi = 0; mi < 2; mi++)
#pragma unroll
        for (int ni = 0; ni < 6; ni++)
#pragma unroll
            for (int j = 0; j < 4; j++) acc[mi][ni][j] = 0.f;

    const int prow = tid >> 2;
    const int psub = tid & 3;
    float4 apf[4];

    auto issueW = [&](int c, int st) {
        const int ko = c * 64;
#pragma unroll
        for (int k = 0; k < 3; k++) {
            const int i = tid + k * 512;
            const int r = i >> 3, g = i & 7;
            cp16(stW[st] + (uint32_t)(r * RSW + g * 4) * 4, Wblk + (size_t)r * CDIM + ko + g * 8);
        }
    };
    auto issueA_h = [&](int c, int st) {
        const int ko = c * 64;
        cp16(stA[st] + (uint32_t)(prow * RSW + psub * 4) * 4,
             Ah + (size_t)prow * CDIM + ko + psub * 8);
        cp16(stA[st] + (uint32_t)(prow * RSW + (psub + 4) * 4) * 4,
             Ah + (size_t)prow * CDIM + ko + (psub + 4) * 8);
    };
    auto ldgA_f = [&](int c) {
        const int ko = c * 64 + psub * 16;
#pragma unroll
        for (int j = 0; j < 4; j++)
            apf[j] = *(const float4*)(Af + (size_t)prow * CDIM + ko + j * 4);
    };
    auto stsA_f = [&](int st) {
        uint32_t* sA = smw + (stA[st] - smb) / 4;
#pragma unroll
        for (int j = 0; j < 4; j++) {
            uint2 p = { h2u(apf[j].x, apf[j].y), h2u(apf[j].z, apf[j].w) };
            *(uint2*)&sA[prow * RSW + psub * 8 + j * 2] = p;
        }
    };

    if (AHALF) { issueA_h(0, 0); } else { ldgA_f(0); }
    issueW(0, 0);
    asm volatile("cp.async.commit_group;" ::: "memory");
    if (!AHALF) stsA_f(0);
    asm volatile("cp.async.wait_group 0;" ::: "memory");
    __syncthreads();

    const uint32_t a_lane = ((uint32_t)(wm * 32 + ((lane >> 3) & 1) * 8 + (lane & 7)) * RSW
                            + (lane >> 4) * 4) * 4;
    const uint32_t b_lane = ((uint32_t)(wn * 48 + (lane >> 4) * 8 + (lane & 7)) * RSW
                            + ((lane >> 3) & 1) * 4) * 4;

#pragma unroll 1
    for (int c = 0; c < 3; c++) {
        const int st = c & 1;
        if (c < 2) {
            if (AHALF) issueA_h(c + 1, st ^ 1); else ldgA_f(c + 1);
            issueW(c + 1, st ^ 1);
            asm volatile("cp.async.commit_group;" ::: "memory");
        }
#pragma unroll
        for (int t = 0; t < 4; t++) {
            uint32_t a[2][4], bb[3][4];
#pragma unroll
            for (int mi = 0; mi < 2; mi++)
                ldsm4(a[mi], stA[st] + a_lane + (uint32_t)(mi * 16 * RSW + t * 8) * 4);
#pragma unroll
            for (int p = 0; p < 3; p++)
                ldsm4(bb[p], stW[st] + b_lane + (uint32_t)(p * 16 * RSW + t * 8) * 4);
#pragma unroll
            for (int p = 0; p < 3; p++) {
                mma_f16(acc[0][2 * p],     a[0], bb[p][0], bb[p][1]);
                mma_f16(acc[1][2 * p],     a[1], bb[p][0], bb[p][1]);
                mma_f16(acc[0][2 * p + 1], a[0], bb[p][2], bb[p][3]);
                mma_f16(acc[1][2 * p + 1], a[1], bb[p][2], bb[p][3]);
            }
        }
        if (c < 2) {
            if (!AHALF) stsA_f(st ^ 1);
            asm volatile("cp.async.wait_group 0;" ::: "memory");
            __syncthreads();
        }
    }

#pragma unroll
    for (int mi = 0; mi < 2; mi++) {
#pragma unroll
        for (int ni = 0; ni < 6; ni++) {
            const size_t row = mbase + wm * 32 + mi * 16 + gid;
            const int    col = nbase + wn * 48 + ni * 8 + tc * 2;
            const float2 bb2 = *(const float2*)&bias[col];
            float v0 = (acc[mi][ni][0] + bb2.x) * outScale;
            float v1 = (acc[mi][ni][1] + bb2.y) * outScale;
            float v2 = (acc[mi][ni][2] + bb2.x) * outScale;
            float v3 = (acc[mi][ni][3] + bb2.y) * outScale;
            if (OHALF) {
                __half* o = (__half*)outv;
                *(uint32_t*)&o[(row    ) * NCTOT + col] = h2u(v0, v1);
                *(uint32_t*)&o[(row + 8) * NCTOT + col] = h2u(v2, v3);
            } else {
                float* o = (float*)outv;
                float2 r0 = {v0, v1}, r1 = {v2, v3};
                *(float2*)&o[(row    ) * NCTOT + col] = r0;
                *(float2*)&o[(row + 8) * NCTOT + col] = r1;
            }
        }
    }
}

// ---------------------------------------------------------------------------
// fp16 attention (R15 layout, proven 294us) + minblocks 8 (cap 128 regs
// -> 16 warps/SM instead of 12).  2 heads/CTA, one warp per head.
// ---------------------------------------------------------------------------
#define HPC     2
#define TSTR    20                                // words per token row
#define OFF_K   (64 * TSTR)                       // 1280
#define OFF_V   (OFF_K + 56 * TSTR)               // 2400
#define OFF_RPB (OFF_V + 64 * TSTR)               // 3680
#define HEADW   (OFF_RPB + 172)                   // 3852 words (16B-aligned)
#define ATTN_SMEM (HPC * HEADW * 4)               // 30816 bytes

__global__ __launch_bounds__(HPC * 32, 8)
void attn_mma(const __half* __restrict__ Q, const __half* __restrict__ KV,
              const float* __restrict__ rpb, __half* __restrict__ O)
{
    extern __shared__ uint32_t smw[];
    const int wid  = threadIdx.x >> 5;
    const int lane = threadIdx.x & 31;
    const int gid  = lane >> 2;
    const int tc   = lane & 3;
    const int bt   = blockIdx.x;
    const int b    = bt >> 1;
    const int h    = blockIdx.y * HPC + wid;

    uint32_t* sQ  = smw + wid * HEADW;
    uint32_t* sK  = sQ + OFF_K;
    uint32_t* sV  = sQ + OFF_V;
    float*    srpb = (float*)(sQ + OFF_RPB);
    const uint32_t sQb = smem_u32(sQ);
    const uint32_t sKb = smem_u32(sK);
    const uint32_t sVb = smem_u32(sV);

    for (int i = lane; i < 169; i += 32) srpb[i] = rpb[i * NHEAD + h];

    const uint4 z4 = {0u, 0u, 0u, 0u};
#pragma unroll
    for (int i = lane; i < 75; i += 32) *(uint4*)&sQ[980 + i * 4] = z4;
#pragma unroll
    for (int i = lane; i < 35; i += 32) *(uint4*)&sK[980 + i * 4] = z4;
#pragma unroll
    for (int i = lane; i < 75; i += 32) *(uint4*)&sV[980 + i * 4] = z4;

    for (int i = lane; i < NTOK * 4; i += 32) {
        const int n = i >> 2, g = i & 3;
        *(uint4*)&sQ[n * TSTR + g * 4] =
            *(const uint4*)&Q[((size_t)(b * NTOK + n)) * CDIM + h * HDIM + g * 8];
        const size_t kb = (size_t)(bt * NTOK + n) * (2 * CDIM) + h * HDIM + g * 8;
        *(uint4*)&sK[n * TSTR + g * 4] = *(const uint4*)&KV[kb];
        *(uint4*)&sV[n * TSTR + g * 4] = *(const uint4*)&KV[kb + CDIM];
    }
    __syncwarp();

    float sf[4][7][4];
#pragma unroll
    for (int mi = 0; mi < 4; mi++)
#pragma unroll
        for (int ni = 0; ni < 7; ni++)
#pragma unroll
            for (int j = 0; j < 4; j++) sf[mi][ni][j] = 0.f;

    const int l15 = lane & 15, l7 = lane & 7;
    const int g16 = lane >> 4, g8 = (lane >> 3) & 1;

#pragma unroll
    for (int t = 0; t < 2; t++) {
        uint32_t a[4][4];
#pragma unroll
        for (int mi = 0; mi < 4; mi++)
            ldsm4(a[mi], sQb + (uint32_t)((16 * mi + l15) * TSTR + t * 8 + g16 * 4) * 4);
        uint32_t bb[4][4];
#pragma unroll
        for (int p = 0; p < 3; p++)
            ldsm4(bb[p], sKb + (uint32_t)((8 * (2 * p + g16) + l7) * TSTR + t * 8 + g8 * 4) * 4);
        ldsm2(bb[3], sKb + (uint32_t)((48 + l7) * TSTR + t * 8 + g8 * 4) * 4);
#pragma unroll
        for (int p = 0; p < 3; p++)
#pragma unroll
            for (int mi = 0; mi < 4; mi++) {
                mma_f16(sf[mi][2 * p],     a[mi], bb[p][0], bb[p][1]);
                mma_f16(sf[mi][2 * p + 1], a[mi], bb[p][2], bb[p][3]);
            }
#pragma unroll
        for (int mi = 0; mi < 4; mi++)
            mma_f16(sf[mi][6], a[mi], bb[3][0], bb[3][1]);
    }

    uint32_t pf[4][4][4];
#pragma unroll
    for (int mi = 0; mi < 4; mi++) {
#pragma unroll
        for (int jp = 0; jp < 2; jp++) {
            const int n = 16 * mi + 8 * jp + gid;
            const bool vrow = (n < NTOK);
            const int fn = 13 * (n / 7) + (n % 7);
            float vv[7][2];
            float mx = -1e30f;
#pragma unroll
            for (int ni = 0; ni < 7; ni++) {
#pragma unroll
                for (int jc = 0; jc < 2; jc++) {
                    const int m = 8 * ni + 2 * tc + jc;
                    float v = sf[mi][ni][jp * 2 + jc];
                    if (vrow && m < NTOK) {
                        const int fm = 13 * (m / 7) + (m % 7);
                        v += srpb[fn - fm + 84];
                    } else {
                        v = -1e30f;
                    }
                    vv[ni][jc] = v;
                    mx = fmaxf(mx, v);
                }
            }
            mx = fmaxf(mx, __shfl_xor_sync(0xffffffffu, mx, 1));
            mx = fmaxf(mx, __shfl_xor_sync(0xffffffffu, mx, 2));
            float sum = 0.f;
#pragma unroll
            for (int ni = 0; ni < 7; ni++)
#pragma unroll
                for (int jc = 0; jc < 2; jc++) {
                    float e = __expf(vv[ni][jc] - mx);
                    vv[ni][jc] = e;
                    sum += e;
                }
            sum += __shfl_xor_sync(0xffffffffu, sum, 1);
            sum += __shfl_xor_sync(0xffffffffu, sum, 2);
            const float inv = vrow ? (1.f / sum) : 0.f;
#pragma unroll
            for (int t = 0; t < 4; t++) {
                pf[mi][t][jp] = h2u(vv[2 * t][0] * inv, vv[2 * t][1] * inv);
                pf[mi][t][2 + jp] = (2 * t + 1 < 7)
                    ? h2u(vv[2 * t + 1][0] * inv, vv[2 * t + 1][1] * inv) : 0u;
            }
        }
    }

    float of[4][4][4];
#pragma unroll
    for (int mi = 0; mi < 4; mi++)
#pragma unroll
        for (int nd = 0; nd < 4; nd++)
#pragma unroll
            for (int j = 0; j < 4; j++) of[mi][nd][j] = 0.f;

#pragma unroll
    for (int t = 0; t < 4; t++) {
        uint32_t bb[2][4];
#pragma unroll
        for (int q = 0; q < 2; q++)
            ldsm4t(bb[q], sVb + (uint32_t)((t * 16 + g8 * 8 + l7) * TSTR + (2 * q + g16) * 4) * 4);
#pragma unroll
        for (int q = 0; q < 2; q++)
#pragma unroll
            for (int mi = 0; mi < 4; mi++) {
                mma_f16(of[mi][2 * q],     pf[mi][t], bb[q][0], bb[q][1]);
                mma_f16(of[mi][2 * q + 1], pf[mi][t], bb[q][2], bb[q][3]);
            }
    }

#pragma unroll
    for (int mi = 0; mi < 4; mi++) {
        const int r0 = 16 * mi + gid;
#pragma unroll
        for (int nd = 0; nd < 4; nd++) {
            const int col = h * HDIM + nd * 8 + 2 * tc;
            if (r0 < NTOK)
                *(uint32_t*)&O[((size_t)(bt * NTOK + r0)) * CDIM + col] =
                    h2u(of[mi][nd][0], of[mi][nd][1]);
            if (r0 + 8 < NTOK)
                *(uint32_t*)&O[((size_t)(bt * NTOK + r0 + 8)) * CDIM + col] =
                    h2u(of[mi][nd][2], of[mi][nd][3]);
        }
    }
}

// ---------------------------------------------------------------------------
// kernel_launch
// ---------------------------------------------------------------------------
extern "C" void kernel_launch(void* const* d_in, const int* in_sizes, int n_in,
                              void* d_out, int out_size)
{
    const float* x      = (const float*)d_in[0];
    const float* memory = (const float*)d_in[1];
    const float* w_q    = (const float*)d_in[2];
    const float* b_q    = (const float*)d_in[3];
    const float* w_kv   = (const float*)d_in[4];
    const float* b_kv   = (const float*)d_in[5];
    const float* w_proj = (const float*)d_in[6];
    const float* b_proj = (const float*)d_in[7];
    const float* rpb    = (const float*)d_in[8];

    __half *gq, *gkv, *gao, *wq16, *wkv16, *wp16;
    cudaGetSymbolAddress((void**)&gq,    g_q);
    cudaGetSymbolAddress((void**)&gkv,   g_kv);
    cudaGetSymbolAddress((void**)&gao,   g_ao);
    cudaGetSymbolAddress((void**)&wq16,  g_wq16);
    cudaGetSymbolAddress((void**)&wkv16, g_wkv16);
    cudaGetSymbolAddress((void**)&wp16,  g_wp16);

    cudaFuncSetAttribute((const void*)gemm_mma<192, false, true>,
                         cudaFuncAttributeMaxDynamicSharedMemorySize, GEMM_SMEM);
    cudaFuncSetAttribute((const void*)gemm_mma<384, false, true>,
                         cudaFuncAttributeMaxDynamicSharedMemorySize, GEMM_SMEM);
    cudaFuncSetAttribute((const void*)gemm_mma<192, true, false>,
                         cudaFuncAttributeMaxDynamicSharedMemorySize, GEMM_SMEM);
    cudaFuncSetAttribute((const void*)attn_mma,
                         cudaFuncAttributeMaxDynamicSharedMemorySize, ATTN_SMEM);

    const float scale = 0.17677669529663687f;   // 32^-0.5, folded into Q

    cvt_w<<<(2 * CDIM * CDIM + 255) / 256, 256>>>(w_q, w_kv, w_proj);

    // Grid layout: x = column block (fast), y = M block (slow)
    gemm_mma<192, false, true><<<dim3(1, M_Q / 128), 512, GEMM_SMEM>>>(
        x, wq16, b_q, gq, scale);
    gemm_mma<384, false, true><<<dim3(2, M_KV / 128), 512, GEMM_SMEM>>>(
        memory, wkv16, b_kv, gkv, 1.0f);
    attn_mma<<<dim3(BATCH * TT, NHEAD / HPC), HPC * 32, ATTN_SMEM>>>(
        gq, gkv, rpb, gao);
    gemm_mma<192, true, false><<<dim3(1, M_KV / 128), 512, GEMM_SMEM>>>(
        gao, wp16, b_proj, d_out, 1.0f);
}